// round 3
// baseline (speedup 1.0000x reference)
#include <cuda_runtime.h>
#include <cuda_fp16.h>
#include <cstdint>

#define N_R   100000
#define N_E   1200000
#define G_N   4096
#define H     64
#define ED    16
#define LYR   4

// ---------------- scratch (device globals; allocation-free) ----------------
__device__ float   g_h[(size_t)N_R * H];
__device__ __half2 g_h16[(size_t)N_R * (H / 2)];
__device__ float   g_agg[(size_t)N_R * H];
__device__ float   g_hs[N_R];
__device__ float   g_hd[N_R];
__device__ float   g_winv[N_R];
__device__ float   g_w[N_E];
__device__ __half2 g_ecsr[(size_t)N_E * (H / 2)];
__device__ float   g_ea[LYR * N_E];
__device__ int     g_deg[N_R];
__device__ int     g_off[N_R + 1];
__device__ int     g_cur[N_R];
__device__ int     g_srcs[N_E];
__device__ int     g_perm[N_E];
__device__ int     g_gcnt[G_N];
__device__ int     g_goff[G_N + 1];
__device__ float   g_w16[LYR * ED];
__device__ float   g_pooled[(size_t)G_N * H];
__device__ int     g_bsums[256];

// ---------------- f32x2 packed-FMA helpers ----------------
__device__ __forceinline__ void ffma2(unsigned long long& d, unsigned long long a,
                                      unsigned long long b, unsigned long long c) {
    asm("fma.rn.f32x2 %0, %1, %2, %3;" : "=l"(d) : "l"(a), "l"(b), "l"(c));
}
__device__ __forceinline__ float2 unpack2(unsigned long long u) {
    float2 f;
    asm("mov.b64 {%0, %1}, %2;" : "=f"(f.x), "=f"(f.y) : "l"(u));
    return f;
}

// ---------------- small utility kernels ----------------
__global__ void zero_int(int* p, int n) {
    int i = blockIdx.x * blockDim.x + threadIdx.x;
    if (i < n) p[i] = 0;
}
__global__ void copy_int(int* dst, const int* src, int n) {
    int i = blockIdx.x * blockDim.x + threadIdx.x;
    if (i < n) dst[i] = src[i];
}
__global__ void hist_kernel(const int* __restrict__ idx, int* __restrict__ cnt, int n) {
    int i = blockIdx.x * blockDim.x + threadIdx.x;
    if (i < n) atomicAdd(&cnt[idx[i]], 1);
}

// ---- multi-block exclusive scan ----
__global__ void scan_block(const int* __restrict__ cnt, int* __restrict__ off,
                           int* __restrict__ sums, int n) {
    __shared__ int wsum[32];
    int tid = threadIdx.x;
    int i = blockIdx.x * 1024 + tid;
    int v = (i < n) ? cnt[i] : 0;
    int x = v;
    #pragma unroll
    for (int d = 1; d < 32; d <<= 1) {
        int y = __shfl_up_sync(0xffffffffu, x, d);
        if ((tid & 31) >= d) x += y;
    }
    if ((tid & 31) == 31) wsum[tid >> 5] = x;
    __syncthreads();
    if (tid < 32) {
        int w = wsum[tid];
        #pragma unroll
        for (int d = 1; d < 32; d <<= 1) {
            int y = __shfl_up_sync(0xffffffffu, w, d);
            if (tid >= d) w += y;
        }
        wsum[tid] = w;
    }
    __syncthreads();
    int incl = x + ((tid >= 32) ? wsum[(tid >> 5) - 1] : 0);
    if (i < n) off[i + 1] = incl;
    if (tid == 1023) sums[blockIdx.x] = incl;
}
__global__ void scan_sums_serial(int* sums, int nb) {
    if (threadIdx.x == 0) {
        int acc = 0;
        for (int b = 0; b < nb; b++) { int t = sums[b]; sums[b] = acc; acc += t; }
    }
}
__global__ void add_base(int* __restrict__ off, const int* __restrict__ sums, int n) {
    int i = blockIdx.x * 1024 + threadIdx.x;
    if (i == 0) off[0] = 0;
    if (i < n) off[i + 1] += sums[blockIdx.x];
}

__global__ void scatter_kernel(const int* __restrict__ src, const int* __restrict__ dst,
                               int* __restrict__ cur, int* __restrict__ perm,
                               int* __restrict__ srcs, int n) {
    int e = blockIdx.x * blockDim.x + threadIdx.x;
    if (e < n) {
        int d = dst[e];
        int p = atomicAdd(&cur[d], 1);
        perm[p] = e;
        srcs[p] = src[e];
    }
}

__global__ void w16_kernel(const float* __restrict__ W_e, const float* __restrict__ a_e,
                           float* __restrict__ w16) {
    int t = threadIdx.x;
    if (t < LYR * ED) {
        int l = t >> 4, k = t & 15;
        float s = 0.f;
        for (int j = 0; j < H; j++) s += W_e[k * H + j] * a_e[l * H + j];
        w16[t] = s;
    }
}

// ---------------- node matvec with packed f32x2 FMA ----------------
// out = maybe_lrelu(resid + in @ W); also writes fp16 mirror + a_s/a_d dots.
__global__ void matvec_kernel(const float* __restrict__ in, const float* __restrict__ W,
                              const float* __restrict__ resid, float* __restrict__ out,
                              __half2* __restrict__ out16,
                              const float* __restrict__ as_, const float* __restrict__ ad_,
                              float* __restrict__ hs, float* __restrict__ hd,
                              int n, int do_lrelu) {
    __shared__ float2 sW2[64 * 32];   // [k][lane] -> the thread's 2 output cols (16KB)
    __shared__ float2 sIn2[64 * 64];  // [node][k] value duplicated into both halves (32KB)
    int tid = threadIdx.x;
    int lane = tid & 31;
    int w = tid >> 5;
    for (int i = tid; i < 2048; i += 256) {
        int k = i >> 5, c = i & 31;
        sW2[i] = make_float2(W[k * 64 + 2 * c], W[k * 64 + 2 * c + 1]);
    }
    float as0 = 0.f, as1 = 0.f, ad0 = 0.f, ad1 = 0.f;
    if (as_) { as0 = as_[2 * lane]; as1 = as_[2 * lane + 1];
               ad0 = ad_[2 * lane]; ad1 = ad_[2 * lane + 1]; }
    const unsigned long long* sWu = (const unsigned long long*)sW2;
    int ntiles = (n + 63) / 64;
    for (int t = blockIdx.x; t < ntiles; t += gridDim.x) {
        int base = t * 64;
        __syncthreads();
        for (int i = tid; i < 4096; i += 256) {
            int node = base + (i >> 6);
            float v = (node < n) ? in[(size_t)node * H + (i & 63)] : 0.f;
            sIn2[i] = make_float2(v, v);
        }
        __syncthreads();
        int r0 = w * 8;
        unsigned long long acc[8];
        #pragma unroll
        for (int r = 0; r < 8; r++) acc[r] = 0ull;
        #pragma unroll 4
        for (int k4 = 0; k4 < 16; k4++) {
            unsigned long long wk0 = sWu[(4 * k4 + 0) * 32 + lane];
            unsigned long long wk1 = sWu[(4 * k4 + 1) * 32 + lane];
            unsigned long long wk2 = sWu[(4 * k4 + 2) * 32 + lane];
            unsigned long long wk3 = sWu[(4 * k4 + 3) * 32 + lane];
            #pragma unroll
            for (int r = 0; r < 8; r++) {
                const ulonglong2* bp = (const ulonglong2*)(sIn2 + (r0 + r) * 64 + 4 * k4);
                ulonglong2 b01 = bp[0];
                ulonglong2 b23 = bp[1];
                ffma2(acc[r], b01.x, wk0, acc[r]);
                ffma2(acc[r], b01.y, wk1, acc[r]);
                ffma2(acc[r], b23.x, wk2, acc[r]);
                ffma2(acc[r], b23.y, wk3, acc[r]);
            }
        }
        #pragma unroll
        for (int r = 0; r < 8; r++) {
            int node = base + r0 + r;
            if (node >= n) break;
            float2 vv = unpack2(acc[r]);
            float v0 = vv.x, v1 = vv.y;
            if (resid) {
                float2 rr = *(const float2*)(resid + (size_t)node * H + 2 * lane);
                v0 += rr.x; v1 += rr.y;
            }
            if (do_lrelu) {
                v0 = v0 > 0.f ? v0 : 0.1f * v0;
                v1 = v1 > 0.f ? v1 : 0.1f * v1;
            }
            *(float2*)(out + (size_t)node * H + 2 * lane) = make_float2(v0, v1);
            out16[(size_t)node * 32 + lane] = __floats2half2_rn(v0, v1);
            if (as_) {
                float ps = v0 * as0 + v1 * as1;
                float pd = v0 * ad0 + v1 * ad1;
                #pragma unroll
                for (int d = 16; d; d >>= 1) {
                    ps += __shfl_xor_sync(0xffffffffu, ps, d);
                    pd += __shfl_xor_sync(0xffffffffu, pd, d);
                }
                if (lane == 0) { hs[node] = ps; hd[node] = pd; }
            }
        }
    }
}

// ---------------- build edge embeddings (fp16, CSR order) + logit terms
__global__ void build_e_kernel(const float* __restrict__ r_edge,
                               const float* __restrict__ W_e,
                               const int* __restrict__ perm,
                               const float* __restrict__ w16,
                               __half2* __restrict__ ecsr, float* __restrict__ ea,
                               int n_e) {
    __shared__ float sWe[ED * H];
    __shared__ float sw16[LYR * ED];
    for (int i = threadIdx.x; i < ED * H; i += 256) sWe[i] = W_e[i];
    if (threadIdx.x < LYR * ED) sw16[threadIdx.x] = w16[threadIdx.x];
    __syncthreads();
    int lane = threadIdx.x & 31;
    int warp = (blockIdx.x * blockDim.x + threadIdx.x) >> 5;
    int nwarps = (gridDim.x * blockDim.x) >> 5;
    const float2* sWe2 = (const float2*)sWe;
    for (int p = warp; p < n_e; p += nwarps) {
        int eid = __ldg(&perm[p]);
        const float4* rp = (const float4*)(r_edge + (size_t)eid * ED);
        float4 q0 = rp[0], q1 = rp[1], q2 = rp[2], q3 = rp[3];
        float r[16] = {q0.x, q0.y, q0.z, q0.w, q1.x, q1.y, q1.z, q1.w,
                       q2.x, q2.y, q2.z, q2.w, q3.x, q3.y, q3.z, q3.w};
        float e0 = 0.f, e1 = 0.f;
        #pragma unroll
        for (int k = 0; k < 16; k++) {
            float2 wp = sWe2[k * 32 + lane];
            e0 += r[k] * wp.x;
            e1 += r[k] * wp.y;
        }
        ecsr[(size_t)p * 32 + lane] = __floats2half2_rn(e0, e1);
        if (lane < LYR) {
            float s = 0.f;
            #pragma unroll
            for (int k = 0; k < 16; k++) s += r[k] * sw16[lane * ED + k];
            ea[(size_t)lane * N_E + p] = s;
        }
    }
}

// ---------------- softmax weights: one THREAD per dst node ----------------
__global__ void weights_kernel(const int* __restrict__ off, const int* __restrict__ srcs,
                               const float* __restrict__ ea, const float* __restrict__ hs,
                               const float* __restrict__ hd,
                               float* __restrict__ w, float* __restrict__ winv, int n) {
    int node = blockIdx.x * blockDim.x + threadIdx.x;
    if (node >= n) return;
    int beg = off[node], end = off[node + 1];
    float hdn = hd[node];
    float m = -1e30f;
    #pragma unroll 4
    for (int p = beg; p < end; p++) {
        float lg = __ldg(&hs[srcs[p]]) + hdn + __ldg(&ea[p]);
        lg = lg > 0.f ? lg : 0.1f * lg;
        w[p] = lg;
        m = fmaxf(m, lg);
    }
    float s = 0.f;
    #pragma unroll 4
    for (int p = beg; p < end; p++) {
        float e = __expf(w[p] - m);
        w[p] = e;
        s += e;
    }
    winv[node] = (end > beg) ? (1.0f / s) : 0.f;
}

// ---------------- weighted gather: one WARP per dst node ----------------
__global__ void gather_kernel(const int* __restrict__ off, const int* __restrict__ srcs,
                              const float* __restrict__ w, const float* __restrict__ winv,
                              const __half2* __restrict__ h16,
                              const __half2* __restrict__ ecsr,
                              float* __restrict__ agg, int n) {
    int node = (blockIdx.x * blockDim.x + threadIdx.x) >> 5;
    int lane = threadIdx.x & 31;
    if (node >= n) return;
    int beg = off[node], end = off[node + 1];
    float v0 = 0.f, v1 = 0.f;
    for (int cs = beg; cs < end; cs += 32) {
        int cnt = min(32, end - cs);
        int p = cs + lane;
        int   sv_r = (p < end) ? __ldg(&srcs[p]) : 0;
        float w_r  = (p < end) ? __ldg(&w[p]) : 0.f;
        #pragma unroll 4
        for (int i = 0; i < cnt; i++) {
            int   sv = __shfl_sync(0xffffffffu, sv_r, i);
            float wv = __shfl_sync(0xffffffffu, w_r, i);
            float2 hp = __half22float2(h16[(size_t)sv * 32 + lane]);
            float2 ep = __half22float2(ecsr[(size_t)(cs + i) * 32 + lane]);
            v0 += wv * (hp.x + ep.x);
            v1 += wv * (hp.y + ep.y);
        }
    }
    float inv = winv[node];
    *(float2*)(agg + (size_t)node * H + 2 * lane) = make_float2(v0 * inv, v1 * inv);
}

// ---------------- gate + interaction mixing + pooling (warp per graph)
__global__ void pool_kernel(const int* __restrict__ goff, const float* __restrict__ d_edge,
                            const float* __restrict__ w_d, const float* __restrict__ b_d,
                            const float* __restrict__ i_node, const float* __restrict__ W_i,
                            const float* __restrict__ h, float* __restrict__ pooled, int g_total) {
    int g = (blockIdx.x * blockDim.x + threadIdx.x) >> 5;
    int lane = threadIdx.x & 31;
    if (g >= g_total) return;
    float wd = w_d[0], bd = b_d[0];
    int beg = goff[g], end = goff[g + 1];
    float s00 = 0.f, s01 = 0.f, s10 = 0.f, s11 = 0.f, sg = 0.f;
    for (int nn = beg; nn < end; nn++) {
        float gate = 1.0f / (1.0f + __expf(-(d_edge[nn] * wd + bd)));
        float2 hp = *(const float2*)(h + (size_t)nn * H + 2 * lane);
        s00 += hp.x; s01 += hp.y;
        s10 += gate * hp.x; s11 += gate * hp.y;
        sg += gate;
    }
    float wi0 = W_i[2 * lane], wi1 = W_i[2 * lane + 1];
    float iv = i_node[g];
    float hi0 = iv * wi0 + s10;
    float hi1 = iv * wi1 + s11;
    *(float2*)(pooled + (size_t)g * H + 2 * lane) =
        make_float2(s00 + sg * hi0, s01 + sg * hi1);
}

// ---------------- MLP readout ----------------
__global__ void mlp_kernel(const float* __restrict__ pooled, const float* __restrict__ W_mlp,
                           const float* __restrict__ b_mlp, const float* __restrict__ W_out,
                           const float* __restrict__ b_out, float* __restrict__ out, int g_total) {
    __shared__ float sW[4096];
    __shared__ float sx[4][64];
    __shared__ float sb[64];
    __shared__ float sWo[64];
    __shared__ float red[8];
    int tid = threadIdx.x;
    int local = tid >> 6, j = tid & 63;
    if (tid < 64) sWo[tid] = W_out[tid];
    int ngroups = (g_total + 3) / 4;
    for (int grp = blockIdx.x; grp < ngroups; grp += gridDim.x) {
        int g = grp * 4 + local;
        __syncthreads();
        sx[local][j] = (g < g_total) ? pooled[(size_t)g * H + j] : 0.f;
        for (int i = 0; i < 3; i++) {
            __syncthreads();
            for (int t = tid; t < 4096; t += 256) sW[t] = W_mlp[i * 4096 + t];
            if (tid < 64) sb[tid] = b_mlp[i * 64 + tid];
            __syncthreads();
            float acc = sb[j];
            for (int k = 0; k < 64; k++) acc += sx[local][k] * sW[k * 64 + j];
            acc = fmaxf(acc, 0.f);
            __syncthreads();
            sx[local][j] = acc;
        }
        __syncthreads();
        float part = sx[local][j] * sWo[j];
        #pragma unroll
        for (int d = 16; d; d >>= 1) part += __shfl_xor_sync(0xffffffffu, part, d);
        if ((tid & 31) == 0) red[tid >> 5] = part;
        __syncthreads();
        if (j == 0 && g < g_total) out[g] = red[2 * local] + red[2 * local + 1] + b_out[0];
    }
}

// ---------------- launcher ----------------
extern "C" void kernel_launch(void* const* d_in, const int* in_sizes, int n_in,
                              void* d_out, int out_size) {
    const float* r_node  = (const float*)d_in[0];
    const float* i_node  = (const float*)d_in[1];
    const float* r_edge  = (const float*)d_in[2];
    const float* d_edge  = (const float*)d_in[3];
    const int*   r2r_src = (const int*)d_in[4];
    const int*   r2r_dst = (const int*)d_in[5];
    const int*   graph_id= (const int*)d_in[6];
    const float* W_r     = (const float*)d_in[7];
    const float* W_i     = (const float*)d_in[8];
    const float* W_e     = (const float*)d_in[9];
    const float* Wm      = (const float*)d_in[10];
    const float* a_s     = (const float*)d_in[11];
    const float* a_d     = (const float*)d_in[12];
    const float* a_e     = (const float*)d_in[13];
    const float* w_d     = (const float*)d_in[14];
    const float* b_d     = (const float*)d_in[15];
    const float* W_mlp   = (const float*)d_in[16];
    const float* b_mlp   = (const float*)d_in[17];
    const float* W_out   = (const float*)d_in[18];
    const float* b_out   = (const float*)d_in[19];
    float* out = (float*)d_out;

    const int nN = in_sizes[3];
    const int nE = in_sizes[4];
    const int nG = in_sizes[1];

    float *p_h, *p_agg, *p_hs, *p_hd, *p_ea, *p_w16, *p_pooled, *p_w, *p_winv;
    __half2 *p_ecsr, *p_h16;
    int *p_deg, *p_off, *p_cur, *p_srcs, *p_perm, *p_gcnt, *p_goff, *p_bsums;
    cudaGetSymbolAddress((void**)&p_h, g_h);
    cudaGetSymbolAddress((void**)&p_h16, g_h16);
    cudaGetSymbolAddress((void**)&p_agg, g_agg);
    cudaGetSymbolAddress((void**)&p_hs, g_hs);
    cudaGetSymbolAddress((void**)&p_hd, g_hd);
    cudaGetSymbolAddress((void**)&p_winv, g_winv);
    cudaGetSymbolAddress((void**)&p_w, g_w);
    cudaGetSymbolAddress((void**)&p_ecsr, g_ecsr);
    cudaGetSymbolAddress((void**)&p_ea, g_ea);
    cudaGetSymbolAddress((void**)&p_w16, g_w16);
    cudaGetSymbolAddress((void**)&p_pooled, g_pooled);
    cudaGetSymbolAddress((void**)&p_deg, g_deg);
    cudaGetSymbolAddress((void**)&p_off, g_off);
    cudaGetSymbolAddress((void**)&p_cur, g_cur);
    cudaGetSymbolAddress((void**)&p_srcs, g_srcs);
    cudaGetSymbolAddress((void**)&p_perm, g_perm);
    cudaGetSymbolAddress((void**)&p_gcnt, g_gcnt);
    cudaGetSymbolAddress((void**)&p_goff, g_goff);
    cudaGetSymbolAddress((void**)&p_bsums, g_bsums);

    // --- CSR build ---
    zero_int<<<(nN + 255) / 256, 256>>>(p_deg, nN);
    zero_int<<<(nG + 255) / 256, 256>>>(p_gcnt, nG);
    hist_kernel<<<(nE + 255) / 256, 256>>>(r2r_dst, p_deg, nE);
    hist_kernel<<<(nN + 255) / 256, 256>>>(graph_id, p_gcnt, nN);

    int nbN = (nN + 1023) / 1024;
    scan_block<<<nbN, 1024>>>(p_deg, p_off, p_bsums, nN);
    scan_sums_serial<<<1, 32>>>(p_bsums, nbN);
    add_base<<<nbN, 1024>>>(p_off, p_bsums, nN);

    int nbG = (nG + 1023) / 1024;
    scan_block<<<nbG, 1024>>>(p_gcnt, p_goff, p_bsums, nG);
    scan_sums_serial<<<1, 32>>>(p_bsums, nbG);
    add_base<<<nbG, 1024>>>(p_goff, p_bsums, nG);

    copy_int<<<(nN + 255) / 256, 256>>>(p_cur, p_off, nN);
    scatter_kernel<<<(nE + 255) / 256, 256>>>(r2r_src, r2r_dst, p_cur, p_perm, p_srcs, nE);

    // --- edge embeddings + logit terms ---
    w16_kernel<<<1, 64>>>(W_e, a_e, p_w16);
    build_e_kernel<<<2048, 256>>>(r_edge, W_e, p_perm, p_w16, p_ecsr, p_ea, nE);

    // --- node embedding ---
    matvec_kernel<<<592, 256>>>(r_node, W_r, nullptr, p_h, p_h16,
                                a_s, a_d, p_hs, p_hd, nN, 0);

    // --- 4 attention conv layers ---
    int gather_blocks = (nN + 7) / 8;
    for (int l = 0; l < LYR; l++) {
        weights_kernel<<<(nN + 255) / 256, 256>>>(p_off, p_srcs, p_ea + (size_t)l * N_E,
                                                  p_hs, p_hd, p_w, p_winv, nN);
        gather_kernel<<<gather_blocks, 256>>>(p_off, p_srcs, p_w, p_winv,
                                              p_h16, p_ecsr, p_agg, nN);
        const float* as_next = (l < LYR - 1) ? (a_s + (l + 1) * H) : nullptr;
        const float* ad_next = (l < LYR - 1) ? (a_d + (l + 1) * H) : nullptr;
        matvec_kernel<<<592, 256>>>(p_agg, Wm + (size_t)l * H * H, p_h, p_h, p_h16,
                                    as_next, ad_next, p_hs, p_hd, nN, 1);
    }

    // --- gate / interaction mixing / pooling ---
    pool_kernel<<<(nG + 7) / 8, 256>>>(p_goff, d_edge, w_d, b_d, i_node, W_i,
                                       p_h, p_pooled, nG);

    // --- MLP readout ---
    mlp_kernel<<<64, 256>>>(p_pooled, W_mlp, b_mlp, W_out, b_out, out, nG);
}

// round 4
// speedup vs baseline: 1.1186x; 1.1186x over previous
#include <cuda_runtime.h>
#include <cuda_fp16.h>
#include <cstdint>

#define N_R   100000
#define N_E   1200000
#define G_N   4096
#define H     64
#define ED    16
#define LYR   4

// ---------------- scratch (device globals; allocation-free) ----------------
__device__ float   g_h[(size_t)N_R * H];
__device__ __half2 g_h16[(size_t)N_R * (H / 2)];
__device__ float   g_agg[(size_t)N_R * H];
__device__ float   g_hs[N_R];
__device__ float   g_hd[N_R];
__device__ float   g_winv[N_R];
__device__ float   g_t[N_E];
__device__ float   g_w[N_E];
__device__ __half2 g_ecsr[(size_t)N_E * (H / 2)];
__device__ float   g_ea[LYR * N_E];
__device__ int     g_deg[N_R];
__device__ int     g_off[N_R + 1];
__device__ int     g_cur[N_R];
__device__ int     g_srcs[N_E];
__device__ int     g_dsts[N_E];
__device__ int     g_perm[N_E];
__device__ int     g_gcnt[G_N];
__device__ int     g_goff[G_N + 1];
__device__ float   g_w16[LYR * ED];
__device__ float   g_pooled[(size_t)G_N * H];
__device__ int     g_bsums[256];

// ---------------- small utility kernels ----------------
__global__ void zero_int(int* p, int n) {
    int i = blockIdx.x * blockDim.x + threadIdx.x;
    if (i < n) p[i] = 0;
}
__global__ void copy_int(int* dst, const int* src, int n) {
    int i = blockIdx.x * blockDim.x + threadIdx.x;
    if (i < n) dst[i] = src[i];
}
__global__ void hist_kernel(const int* __restrict__ idx, int* __restrict__ cnt, int n) {
    int i = blockIdx.x * blockDim.x + threadIdx.x;
    if (i < n) atomicAdd(&cnt[idx[i]], 1);
}

// ---- multi-block exclusive scan ----
__global__ void scan_block(const int* __restrict__ cnt, int* __restrict__ off,
                           int* __restrict__ sums, int n) {
    __shared__ int wsum[32];
    int tid = threadIdx.x;
    int i = blockIdx.x * 1024 + tid;
    int v = (i < n) ? cnt[i] : 0;
    int x = v;
    #pragma unroll
    for (int d = 1; d < 32; d <<= 1) {
        int y = __shfl_up_sync(0xffffffffu, x, d);
        if ((tid & 31) >= d) x += y;
    }
    if ((tid & 31) == 31) wsum[tid >> 5] = x;
    __syncthreads();
    if (tid < 32) {
        int w = wsum[tid];
        #pragma unroll
        for (int d = 1; d < 32; d <<= 1) {
            int y = __shfl_up_sync(0xffffffffu, w, d);
            if (tid >= d) w += y;
        }
        wsum[tid] = w;
    }
    __syncthreads();
    int incl = x + ((tid >= 32) ? wsum[(tid >> 5) - 1] : 0);
    if (i < n) off[i + 1] = incl;
    if (tid == 1023) sums[blockIdx.x] = incl;
}
__global__ void scan_sums_serial(int* sums, int nb) {
    if (threadIdx.x == 0) {
        int acc = 0;
        for (int b = 0; b < nb; b++) { int t = sums[b]; sums[b] = acc; acc += t; }
    }
}
__global__ void add_base(int* __restrict__ off, const int* __restrict__ sums, int n) {
    int i = blockIdx.x * 1024 + threadIdx.x;
    if (i == 0) off[0] = 0;
    if (i < n) off[i + 1] += sums[blockIdx.x];
}

__global__ void scatter_kernel(const int* __restrict__ src, const int* __restrict__ dst,
                               int* __restrict__ cur, int* __restrict__ perm,
                               int* __restrict__ srcs, int* __restrict__ dsts, int n) {
    int e = blockIdx.x * blockDim.x + threadIdx.x;
    if (e < n) {
        int d = dst[e];
        int p = atomicAdd(&cur[d], 1);
        perm[p] = e;
        srcs[p] = src[e];
        dsts[p] = d;
    }
}

__global__ void w16_kernel(const float* __restrict__ W_e, const float* __restrict__ a_e,
                           float* __restrict__ w16) {
    int t = threadIdx.x;
    if (t < LYR * ED) {
        int l = t >> 4, k = t & 15;
        float s = 0.f;
        for (int j = 0; j < H; j++) s += W_e[k * H + j] * a_e[l * H + j];
        w16[t] = s;
    }
}

// ---------------- node matvec (R2-proven) + fp16 mirror ----------------
__global__ void matvec_kernel(const float* __restrict__ in, const float* __restrict__ W,
                              const float* __restrict__ resid, float* __restrict__ out,
                              __half2* __restrict__ out16,
                              const float* __restrict__ as_, const float* __restrict__ ad_,
                              float* __restrict__ hs, float* __restrict__ hd,
                              int n, int do_lrelu) {
    __shared__ float sW[64 * 64];
    __shared__ float sIn[64 * 64];
    for (int i = threadIdx.x; i < 4096; i += 256) sW[i] = W[i];
    int lane = threadIdx.x & 31;
    int w = threadIdx.x >> 5;
    float as0 = 0.f, as1 = 0.f, ad0 = 0.f, ad1 = 0.f;
    if (as_) { as0 = as_[2 * lane]; as1 = as_[2 * lane + 1];
               ad0 = ad_[2 * lane]; ad1 = ad_[2 * lane + 1]; }
    const float2* sW2 = (const float2*)sW;
    int ntiles = (n + 63) / 64;
    for (int t = blockIdx.x; t < ntiles; t += gridDim.x) {
        int base = t * 64;
        __syncthreads();
        for (int i = threadIdx.x; i < 4096; i += 256) {
            int node = base + (i >> 6);
            sIn[i] = (node < n) ? in[(size_t)node * H + (i & 63)] : 0.f;
        }
        __syncthreads();
        int r0 = w * 8;
        float acc[8][2];
        #pragma unroll
        for (int r = 0; r < 8; r++) { acc[r][0] = 0.f; acc[r][1] = 0.f; }
        for (int k = 0; k < 64; k++) {
            float2 wp = sW2[k * 32 + lane];
            #pragma unroll
            for (int r = 0; r < 8; r++) {
                float b = sIn[(r0 + r) * 64 + k];
                acc[r][0] += b * wp.x;
                acc[r][1] += b * wp.y;
            }
        }
        #pragma unroll
        for (int r = 0; r < 8; r++) {
            int node = base + r0 + r;
            if (node >= n) break;
            float v0 = acc[r][0], v1 = acc[r][1];
            if (resid) {
                float2 rr = *(const float2*)(resid + (size_t)node * H + 2 * lane);
                v0 += rr.x; v1 += rr.y;
            }
            if (do_lrelu) {
                v0 = v0 > 0.f ? v0 : 0.1f * v0;
                v1 = v1 > 0.f ? v1 : 0.1f * v1;
            }
            *(float2*)(out + (size_t)node * H + 2 * lane) = make_float2(v0, v1);
            out16[(size_t)node * 32 + lane] = __floats2half2_rn(v0, v1);
            if (as_) {
                float ps = v0 * as0 + v1 * as1;
                float pd = v0 * ad0 + v1 * ad1;
                #pragma unroll
                for (int d = 16; d; d >>= 1) {
                    ps += __shfl_xor_sync(0xffffffffu, ps, d);
                    pd += __shfl_xor_sync(0xffffffffu, pd, d);
                }
                if (lane == 0) { hs[node] = ps; hd[node] = pd; }
            }
        }
    }
}

// ---------------- build edge embeddings (fp16, CSR order) + logit terms
__global__ void build_e_kernel(const float* __restrict__ r_edge,
                               const float* __restrict__ W_e,
                               const int* __restrict__ perm,
                               const float* __restrict__ w16,
                               __half2* __restrict__ ecsr, float* __restrict__ ea,
                               int n_e) {
    __shared__ float sWe[ED * H];
    __shared__ float sw16[LYR * ED];
    for (int i = threadIdx.x; i < ED * H; i += 256) sWe[i] = W_e[i];
    if (threadIdx.x < LYR * ED) sw16[threadIdx.x] = w16[threadIdx.x];
    __syncthreads();
    int lane = threadIdx.x & 31;
    int warp = (blockIdx.x * blockDim.x + threadIdx.x) >> 5;
    int nwarps = (gridDim.x * blockDim.x) >> 5;
    const float2* sWe2 = (const float2*)sWe;
    for (int p = warp; p < n_e; p += nwarps) {
        int eid = __ldg(&perm[p]);
        const float4* rp = (const float4*)(r_edge + (size_t)eid * ED);
        float4 q0 = rp[0], q1 = rp[1], q2 = rp[2], q3 = rp[3];
        float r[16] = {q0.x, q0.y, q0.z, q0.w, q1.x, q1.y, q1.z, q1.w,
                       q2.x, q2.y, q2.z, q2.w, q3.x, q3.y, q3.z, q3.w};
        float e0 = 0.f, e1 = 0.f;
        #pragma unroll
        for (int k = 0; k < 16; k++) {
            float2 wp = sWe2[k * 32 + lane];
            e0 += r[k] * wp.x;
            e1 += r[k] * wp.y;
        }
        ecsr[(size_t)p * 32 + lane] = __floats2half2_rn(e0, e1);
        if (lane < LYR) {
            float s = 0.f;
            #pragma unroll
            for (int k = 0; k < 16; k++) s += r[k] * sw16[lane * ED + k];
            ea[(size_t)lane * N_E + p] = s;
        }
    }
}

// ---------------- edge-parallel logits: t[p] = lrelu(hs[src]+hd[dst]+ea[p])
__global__ void logits_kernel(const int* __restrict__ srcs, const int* __restrict__ dsts,
                              const float* __restrict__ ea, const float* __restrict__ hs,
                              const float* __restrict__ hd, float* __restrict__ t, int n_e) {
    int p = blockIdx.x * blockDim.x + threadIdx.x;
    if (p >= n_e) return;
    float lg = __ldg(&hs[srcs[p]]) + __ldg(&hd[dsts[p]]) + ea[p];
    t[p] = lg > 0.f ? lg : 0.1f * lg;
}

// ---------------- node-parallel normalize: w[p]=exp(t[p]-m), winv=1/sum
__global__ void norm_kernel(const int* __restrict__ off, const float* __restrict__ t,
                            float* __restrict__ w, float* __restrict__ winv, int n) {
    int node = blockIdx.x * blockDim.x + threadIdx.x;
    if (node >= n) return;
    int beg = off[node], end = off[node + 1];
    float m = -1e30f;
    for (int p = beg; p < end; p++) m = fmaxf(m, __ldg(&t[p]));
    float s = 0.f;
    for (int p = beg; p < end; p++) {
        float e = __expf(__ldg(&t[p]) - m);
        w[p] = e;
        s += e;
    }
    winv[node] = (end > beg) ? (1.0f / s) : 0.f;
}

// ---------------- weighted gather: warp per dst node, dual accumulators
__global__ void gather_kernel(const int* __restrict__ off, const int* __restrict__ srcs,
                              const float* __restrict__ w, const float* __restrict__ winv,
                              const __half2* __restrict__ h16,
                              const __half2* __restrict__ ecsr,
                              float* __restrict__ agg, int n) {
    int node = (blockIdx.x * blockDim.x + threadIdx.x) >> 5;
    int lane = threadIdx.x & 31;
    if (node >= n) return;
    int beg = off[node], end = off[node + 1];
    float a0 = 0.f, a1 = 0.f, b0 = 0.f, b1 = 0.f;
    int p = beg;
    for (; p + 2 <= end; p += 2) {
        float w0 = __ldg(&w[p]);
        float w1 = __ldg(&w[p + 1]);
        int   s0 = __ldg(&srcs[p]);
        int   s1 = __ldg(&srcs[p + 1]);
        float2 h0 = __half22float2(h16[(size_t)s0 * 32 + lane]);
        float2 e0 = __half22float2(ecsr[(size_t)p * 32 + lane]);
        float2 h1 = __half22float2(h16[(size_t)s1 * 32 + lane]);
        float2 e1 = __half22float2(ecsr[(size_t)(p + 1) * 32 + lane]);
        a0 += w0 * (h0.x + e0.x);
        a1 += w0 * (h0.y + e0.y);
        b0 += w1 * (h1.x + e1.x);
        b1 += w1 * (h1.y + e1.y);
    }
    if (p < end) {
        float w0 = __ldg(&w[p]);
        int   s0 = __ldg(&srcs[p]);
        float2 h0 = __half22float2(h16[(size_t)s0 * 32 + lane]);
        float2 e0 = __half22float2(ecsr[(size_t)p * 32 + lane]);
        a0 += w0 * (h0.x + e0.x);
        a1 += w0 * (h0.y + e0.y);
    }
    float inv = winv[node];
    *(float2*)(agg + (size_t)node * H + 2 * lane) =
        make_float2((a0 + b0) * inv, (a1 + b1) * inv);
}

// ---------------- gate + interaction mixing + pooling (warp per graph)
__global__ void pool_kernel(const int* __restrict__ goff, const float* __restrict__ d_edge,
                            const float* __restrict__ w_d, const float* __restrict__ b_d,
                            const float* __restrict__ i_node, const float* __restrict__ W_i,
                            const float* __restrict__ h, float* __restrict__ pooled, int g_total) {
    int g = (blockIdx.x * blockDim.x + threadIdx.x) >> 5;
    int lane = threadIdx.x & 31;
    if (g >= g_total) return;
    float wd = w_d[0], bd = b_d[0];
    int beg = goff[g], end = goff[g + 1];
    float s00 = 0.f, s01 = 0.f, s10 = 0.f, s11 = 0.f, sg = 0.f;
    for (int nn = beg; nn < end; nn++) {
        float gate = 1.0f / (1.0f + __expf(-(d_edge[nn] * wd + bd)));
        float2 hp = *(const float2*)(h + (size_t)nn * H + 2 * lane);
        s00 += hp.x; s01 += hp.y;
        s10 += gate * hp.x; s11 += gate * hp.y;
        sg += gate;
    }
    float wi0 = W_i[2 * lane], wi1 = W_i[2 * lane + 1];
    float iv = i_node[g];
    float hi0 = iv * wi0 + s10;
    float hi1 = iv * wi1 + s11;
    *(float2*)(pooled + (size_t)g * H + 2 * lane) =
        make_float2(s00 + sg * hi0, s01 + sg * hi1);
}

// ---------------- MLP readout ----------------
__global__ void mlp_kernel(const float* __restrict__ pooled, const float* __restrict__ W_mlp,
                           const float* __restrict__ b_mlp, const float* __restrict__ W_out,
                           const float* __restrict__ b_out, float* __restrict__ out, int g_total) {
    __shared__ float sW[4096];
    __shared__ float sx[4][64];
    __shared__ float sb[64];
    __shared__ float sWo[64];
    __shared__ float red[8];
    int tid = threadIdx.x;
    int local = tid >> 6, j = tid & 63;
    if (tid < 64) sWo[tid] = W_out[tid];
    int ngroups = (g_total + 3) / 4;
    for (int grp = blockIdx.x; grp < ngroups; grp += gridDim.x) {
        int g = grp * 4 + local;
        __syncthreads();
        sx[local][j] = (g < g_total) ? pooled[(size_t)g * H + j] : 0.f;
        for (int i = 0; i < 3; i++) {
            __syncthreads();
            for (int t = tid; t < 4096; t += 256) sW[t] = W_mlp[i * 4096 + t];
            if (tid < 64) sb[tid] = b_mlp[i * 64 + tid];
            __syncthreads();
            float acc = sb[j];
            for (int k = 0; k < 64; k++) acc += sx[local][k] * sW[k * 64 + j];
            acc = fmaxf(acc, 0.f);
            __syncthreads();
            sx[local][j] = acc;
        }
        __syncthreads();
        float part = sx[local][j] * sWo[j];
        #pragma unroll
        for (int d = 16; d; d >>= 1) part += __shfl_xor_sync(0xffffffffu, part, d);
        if ((tid & 31) == 0) red[tid >> 5] = part;
        __syncthreads();
        if (j == 0 && g < g_total) out[g] = red[2 * local] + red[2 * local + 1] + b_out[0];
    }
}

// ---------------- launcher ----------------
extern "C" void kernel_launch(void* const* d_in, const int* in_sizes, int n_in,
                              void* d_out, int out_size) {
    const float* r_node  = (const float*)d_in[0];
    const float* i_node  = (const float*)d_in[1];
    const float* r_edge  = (const float*)d_in[2];
    const float* d_edge  = (const float*)d_in[3];
    const int*   r2r_src = (const int*)d_in[4];
    const int*   r2r_dst = (const int*)d_in[5];
    const int*   graph_id= (const int*)d_in[6];
    const float* W_r     = (const float*)d_in[7];
    const float* W_i     = (const float*)d_in[8];
    const float* W_e     = (const float*)d_in[9];
    const float* Wm      = (const float*)d_in[10];
    const float* a_s     = (const float*)d_in[11];
    const float* a_d     = (const float*)d_in[12];
    const float* a_e     = (const float*)d_in[13];
    const float* w_d     = (const float*)d_in[14];
    const float* b_d     = (const float*)d_in[15];
    const float* W_mlp   = (const float*)d_in[16];
    const float* b_mlp   = (const float*)d_in[17];
    const float* W_out   = (const float*)d_in[18];
    const float* b_out   = (const float*)d_in[19];
    float* out = (float*)d_out;

    const int nN = in_sizes[3];
    const int nE = in_sizes[4];
    const int nG = in_sizes[1];

    float *p_h, *p_agg, *p_hs, *p_hd, *p_ea, *p_w16, *p_pooled, *p_w, *p_winv, *p_t;
    __half2 *p_ecsr, *p_h16;
    int *p_deg, *p_off, *p_cur, *p_srcs, *p_dsts, *p_perm, *p_gcnt, *p_goff, *p_bsums;
    cudaGetSymbolAddress((void**)&p_h, g_h);
    cudaGetSymbolAddress((void**)&p_h16, g_h16);
    cudaGetSymbolAddress((void**)&p_agg, g_agg);
    cudaGetSymbolAddress((void**)&p_hs, g_hs);
    cudaGetSymbolAddress((void**)&p_hd, g_hd);
    cudaGetSymbolAddress((void**)&p_winv, g_winv);
    cudaGetSymbolAddress((void**)&p_t, g_t);
    cudaGetSymbolAddress((void**)&p_w, g_w);
    cudaGetSymbolAddress((void**)&p_ecsr, g_ecsr);
    cudaGetSymbolAddress((void**)&p_ea, g_ea);
    cudaGetSymbolAddress((void**)&p_w16, g_w16);
    cudaGetSymbolAddress((void**)&p_pooled, g_pooled);
    cudaGetSymbolAddress((void**)&p_deg, g_deg);
    cudaGetSymbolAddress((void**)&p_off, g_off);
    cudaGetSymbolAddress((void**)&p_cur, g_cur);
    cudaGetSymbolAddress((void**)&p_srcs, g_srcs);
    cudaGetSymbolAddress((void**)&p_dsts, g_dsts);
    cudaGetSymbolAddress((void**)&p_perm, g_perm);
    cudaGetSymbolAddress((void**)&p_gcnt, g_gcnt);
    cudaGetSymbolAddress((void**)&p_goff, g_goff);
    cudaGetSymbolAddress((void**)&p_bsums, g_bsums);

    // --- CSR build ---
    zero_int<<<(nN + 255) / 256, 256>>>(p_deg, nN);
    zero_int<<<(nG + 255) / 256, 256>>>(p_gcnt, nG);
    hist_kernel<<<(nE + 255) / 256, 256>>>(r2r_dst, p_deg, nE);
    hist_kernel<<<(nN + 255) / 256, 256>>>(graph_id, p_gcnt, nN);

    int nbN = (nN + 1023) / 1024;
    scan_block<<<nbN, 1024>>>(p_deg, p_off, p_bsums, nN);
    scan_sums_serial<<<1, 32>>>(p_bsums, nbN);
    add_base<<<nbN, 1024>>>(p_off, p_bsums, nN);

    int nbG = (nG + 1023) / 1024;
    scan_block<<<nbG, 1024>>>(p_gcnt, p_goff, p_bsums, nG);
    scan_sums_serial<<<1, 32>>>(p_bsums, nbG);
    add_base<<<nbG, 1024>>>(p_goff, p_bsums, nG);

    copy_int<<<(nN + 255) / 256, 256>>>(p_cur, p_off, nN);
    scatter_kernel<<<(nE + 255) / 256, 256>>>(r2r_src, r2r_dst, p_cur, p_perm,
                                              p_srcs, p_dsts, nE);

    // --- edge embeddings + logit terms ---
    w16_kernel<<<1, 64>>>(W_e, a_e, p_w16);
    build_e_kernel<<<2048, 256>>>(r_edge, W_e, p_perm, p_w16, p_ecsr, p_ea, nE);

    // --- node embedding ---
    matvec_kernel<<<592, 256>>>(r_node, W_r, nullptr, p_h, p_h16,
                                a_s, a_d, p_hs, p_hd, nN, 0);

    // --- 4 attention conv layers ---
    int gather_blocks = (nN + 7) / 8;
    for (int l = 0; l < LYR; l++) {
        logits_kernel<<<(nE + 255) / 256, 256>>>(p_srcs, p_dsts, p_ea + (size_t)l * N_E,
                                                 p_hs, p_hd, p_t, nE);
        norm_kernel<<<(nN + 255) / 256, 256>>>(p_off, p_t, p_w, p_winv, nN);
        gather_kernel<<<gather_blocks, 256>>>(p_off, p_srcs, p_w, p_winv,
                                              p_h16, p_ecsr, p_agg, nN);
        const float* as_next = (l < LYR - 1) ? (a_s + (l + 1) * H) : nullptr;
        const float* ad_next = (l < LYR - 1) ? (a_d + (l + 1) * H) : nullptr;
        matvec_kernel<<<592, 256>>>(p_agg, Wm + (size_t)l * H * H, p_h, p_h, p_h16,
                                    as_next, ad_next, p_hs, p_hd, nN, 1);
    }

    // --- gate / interaction mixing / pooling ---
    pool_kernel<<<(nG + 7) / 8, 256>>>(p_goff, d_edge, w_d, b_d, i_node, W_i,
                                       p_h, p_pooled, nG);

    // --- MLP readout ---
    mlp_kernel<<<64, 256>>>(p_pooled, W_mlp, b_mlp, W_out, b_out, out, nG);
}

// round 5
// speedup vs baseline: 1.1638x; 1.0404x over previous
#include <cuda_runtime.h>
#include <cuda_fp16.h>
#include <cstdint>

#define N_R   100000
#define N_E   1200000
#define G_N   4096
#define H     64
#define ED    16
#define LYR   4
#define CHUNK 128

// ---------------- scratch (device globals; allocation-free) ----------------
__device__ float   g_h[(size_t)N_R * H];
__device__ __half2 g_h16[(size_t)N_R * (H / 2)];
__device__ float   g_agg[(size_t)N_R * H];
__device__ float   g_hs[N_R];
__device__ float   g_hd[N_R];
__device__ __half2 g_ecsr[(size_t)N_E * (H / 2)];
__device__ float   g_ea[LYR * N_E];
__device__ int     g_deg[N_R];
__device__ int     g_off[N_R + 1];
__device__ int     g_cur[N_R];
__device__ int     g_srcs[N_E];
__device__ int     g_perm[N_E];
__device__ int     g_gcnt[G_N];
__device__ int     g_goff[G_N + 1];
__device__ float   g_w16[LYR * ED];
__device__ float   g_pooled[(size_t)G_N * H];
__device__ int     g_bsums[256];

// ---------------- small utility kernels ----------------
__global__ void zero_int(int* p, int n) {
    int i = blockIdx.x * blockDim.x + threadIdx.x;
    if (i < n) p[i] = 0;
}
__global__ void copy_int(int* dst, const int* src, int n) {
    int i = blockIdx.x * blockDim.x + threadIdx.x;
    if (i < n) dst[i] = src[i];
}
__global__ void hist_kernel(const int* __restrict__ idx, int* __restrict__ cnt, int n) {
    int i = blockIdx.x * blockDim.x + threadIdx.x;
    if (i < n) atomicAdd(&cnt[idx[i]], 1);
}

// ---- multi-block exclusive scan ----
__global__ void scan_block(const int* __restrict__ cnt, int* __restrict__ off,
                           int* __restrict__ sums, int n) {
    __shared__ int wsum[32];
    int tid = threadIdx.x;
    int i = blockIdx.x * 1024 + tid;
    int v = (i < n) ? cnt[i] : 0;
    int x = v;
    #pragma unroll
    for (int d = 1; d < 32; d <<= 1) {
        int y = __shfl_up_sync(0xffffffffu, x, d);
        if ((tid & 31) >= d) x += y;
    }
    if ((tid & 31) == 31) wsum[tid >> 5] = x;
    __syncthreads();
    if (tid < 32) {
        int w = wsum[tid];
        #pragma unroll
        for (int d = 1; d < 32; d <<= 1) {
            int y = __shfl_up_sync(0xffffffffu, w, d);
            if (tid >= d) w += y;
        }
        wsum[tid] = w;
    }
    __syncthreads();
    int incl = x + ((tid >= 32) ? wsum[(tid >> 5) - 1] : 0);
    if (i < n) off[i + 1] = incl;
    if (tid == 1023) sums[blockIdx.x] = incl;
}
__global__ void scan_sums_serial(int* sums, int nb) {
    if (threadIdx.x == 0) {
        int acc = 0;
        for (int b = 0; b < nb; b++) { int t = sums[b]; sums[b] = acc; acc += t; }
    }
}
__global__ void add_base(int* __restrict__ off, const int* __restrict__ sums, int n) {
    int i = blockIdx.x * 1024 + threadIdx.x;
    if (i == 0) off[0] = 0;
    if (i < n) off[i + 1] += sums[blockIdx.x];
}

__global__ void scatter_kernel(const int* __restrict__ src, const int* __restrict__ dst,
                               int* __restrict__ cur, int* __restrict__ perm,
                               int* __restrict__ srcs, int n) {
    int e = blockIdx.x * blockDim.x + threadIdx.x;
    if (e < n) {
        int d = dst[e];
        int p = atomicAdd(&cur[d], 1);
        perm[p] = e;
        srcs[p] = src[e];
    }
}

__global__ void w16_kernel(const float* __restrict__ W_e, const float* __restrict__ a_e,
                           float* __restrict__ w16) {
    int t = threadIdx.x;
    if (t < LYR * ED) {
        int l = t >> 4, k = t & 15;
        float s = 0.f;
        for (int j = 0; j < H; j++) s += W_e[k * H + j] * a_e[l * H + j];
        w16[t] = s;
    }
}

// ---------------- node matvec (R2-proven) + fp16 mirror ----------------
__global__ void __launch_bounds__(256)
matvec_kernel(const float* __restrict__ in, const float* __restrict__ W,
              const float* __restrict__ resid, float* __restrict__ out,
              __half2* __restrict__ out16,
              const float* __restrict__ as_, const float* __restrict__ ad_,
              float* __restrict__ hs, float* __restrict__ hd,
              int n, int do_lrelu) {
    __shared__ float sW[64 * 64];
    __shared__ float sIn[64 * 64];
    for (int i = threadIdx.x; i < 4096; i += 256) sW[i] = W[i];
    int lane = threadIdx.x & 31;
    int w = threadIdx.x >> 5;
    float as0 = 0.f, as1 = 0.f, ad0 = 0.f, ad1 = 0.f;
    if (as_) { as0 = as_[2 * lane]; as1 = as_[2 * lane + 1];
               ad0 = ad_[2 * lane]; ad1 = ad_[2 * lane + 1]; }
    const float2* sW2 = (const float2*)sW;
    int ntiles = (n + 63) / 64;
    for (int t = blockIdx.x; t < ntiles; t += gridDim.x) {
        int base = t * 64;
        __syncthreads();
        for (int i = threadIdx.x; i < 4096; i += 256) {
            int node = base + (i >> 6);
            sIn[i] = (node < n) ? in[(size_t)node * H + (i & 63)] : 0.f;
        }
        __syncthreads();
        int r0 = w * 8;
        float acc[8][2];
        #pragma unroll
        for (int r = 0; r < 8; r++) { acc[r][0] = 0.f; acc[r][1] = 0.f; }
        for (int k = 0; k < 64; k++) {
            float2 wp = sW2[k * 32 + lane];
            #pragma unroll
            for (int r = 0; r < 8; r++) {
                float b = sIn[(r0 + r) * 64 + k];
                acc[r][0] += b * wp.x;
                acc[r][1] += b * wp.y;
            }
        }
        #pragma unroll
        for (int r = 0; r < 8; r++) {
            int node = base + r0 + r;
            if (node >= n) break;
            float v0 = acc[r][0], v1 = acc[r][1];
            if (resid) {
                float2 rr = *(const float2*)(resid + (size_t)node * H + 2 * lane);
                v0 += rr.x; v1 += rr.y;
            }
            if (do_lrelu) {
                v0 = v0 > 0.f ? v0 : 0.1f * v0;
                v1 = v1 > 0.f ? v1 : 0.1f * v1;
            }
            *(float2*)(out + (size_t)node * H + 2 * lane) = make_float2(v0, v1);
            out16[(size_t)node * 32 + lane] = __floats2half2_rn(v0, v1);
            if (as_) {
                float ps = v0 * as0 + v1 * as1;
                float pd = v0 * ad0 + v1 * ad1;
                #pragma unroll
                for (int d = 16; d; d >>= 1) {
                    ps += __shfl_xor_sync(0xffffffffu, ps, d);
                    pd += __shfl_xor_sync(0xffffffffu, pd, d);
                }
                if (lane == 0) { hs[node] = ps; hd[node] = pd; }
            }
        }
    }
}

// ---------------- build edge embeddings (fp16, CSR order) + logit terms
__global__ void __launch_bounds__(256)
build_e_kernel(const float* __restrict__ r_edge,
               const float* __restrict__ W_e,
               const int* __restrict__ perm,
               const float* __restrict__ w16,
               __half2* __restrict__ ecsr, float* __restrict__ ea,
               int n_e) {
    __shared__ float sWe[ED * H];
    __shared__ float sw16[LYR * ED];
    for (int i = threadIdx.x; i < ED * H; i += 256) sWe[i] = W_e[i];
    if (threadIdx.x < LYR * ED) sw16[threadIdx.x] = w16[threadIdx.x];
    __syncthreads();
    int lane = threadIdx.x & 31;
    int warp = (blockIdx.x * blockDim.x + threadIdx.x) >> 5;
    int nwarps = (gridDim.x * blockDim.x) >> 5;
    const float2* sWe2 = (const float2*)sWe;
    for (int p = warp; p < n_e; p += nwarps) {
        int eid = __ldg(&perm[p]);
        const float4* rp = (const float4*)(r_edge + (size_t)eid * ED);
        float4 q0 = rp[0], q1 = rp[1], q2 = rp[2], q3 = rp[3];
        float r[16] = {q0.x, q0.y, q0.z, q0.w, q1.x, q1.y, q1.z, q1.w,
                       q2.x, q2.y, q2.z, q2.w, q3.x, q3.y, q3.z, q3.w};
        float e0 = 0.f, e1 = 0.f;
        #pragma unroll
        for (int k = 0; k < 16; k++) {
            float2 wp = sWe2[k * 32 + lane];
            e0 += r[k] * wp.x;
            e1 += r[k] * wp.y;
        }
        ecsr[(size_t)p * 32 + lane] = __floats2half2_rn(e0, e1);
        if (lane < LYR) {
            float s = 0.f;
            #pragma unroll
            for (int k = 0; k < 16; k++) s += r[k] * sw16[lane * ED + k];
            ea[(size_t)lane * N_E + p] = s;
        }
    }
}

// ---------------- fused attention layer (R2 structure, h16 gather) ----------------
__global__ void __launch_bounds__(256)
layer_kernel(const int* __restrict__ off, const int* __restrict__ srcs,
             const float* __restrict__ ea, const float* __restrict__ hs,
             const float* __restrict__ hd, const __half2* __restrict__ h16,
             const __half2* __restrict__ ecsr, float* __restrict__ agg, int n) {
    __shared__ float s_w[8][CHUNK];
    __shared__ int   s_src[8][CHUNK];
    int wl = threadIdx.x >> 5;
    int lane = threadIdx.x & 31;
    int node = (blockIdx.x * blockDim.x + threadIdx.x) >> 5;
    if (node >= n) return;
    int beg = off[node], end = off[node + 1];
    float hdn = hd[node];
    float m_run = -1e30f, s_run = 0.f, v0 = 0.f, v1 = 0.f;
    for (int cs = beg; cs < end; cs += CHUNK) {
        int cnt = min(CHUNK, end - cs);
        // scalar phase: logits
        float mloc = -1e30f;
        for (int i = lane; i < cnt; i += 32) {
            int p = cs + i;
            int sv = __ldg(&srcs[p]);
            float lg = __ldg(&hs[sv]) + hdn + __ldg(&ea[p]);
            lg = lg > 0.f ? lg : 0.1f * lg;
            s_w[wl][i] = lg;
            s_src[wl][i] = sv;
            mloc = fmaxf(mloc, lg);
        }
        #pragma unroll
        for (int d = 16; d; d >>= 1) mloc = fmaxf(mloc, __shfl_xor_sync(0xffffffffu, mloc, d));
        float mn = fmaxf(m_run, mloc);
        __syncwarp();
        float sloc = 0.f;
        for (int i = lane; i < cnt; i += 32) {
            float wv = __expf(s_w[wl][i] - mn);
            s_w[wl][i] = wv;
            sloc += wv;
        }
        #pragma unroll
        for (int d = 16; d; d >>= 1) sloc += __shfl_xor_sync(0xffffffffu, sloc, d);
        float c = __expf(m_run - mn);
        s_run = s_run * c + sloc;
        v0 *= c; v1 *= c;
        __syncwarp();
        // vector phase: independent per-edge accumulation (fp16 operands)
        #pragma unroll 4
        for (int i = 0; i < cnt; i++) {
            float wv = s_w[wl][i];
            int sv = s_src[wl][i];
            float2 hp = __half22float2(h16[(size_t)sv * 32 + lane]);
            float2 ep = __half22float2(ecsr[(size_t)(cs + i) * 32 + lane]);
            v0 += wv * (hp.x + ep.x);
            v1 += wv * (hp.y + ep.y);
        }
        m_run = mn;
    }
    float inv = (end > beg) ? (1.0f / s_run) : 0.f;
    *(float2*)(agg + (size_t)node * H + 2 * lane) = make_float2(v0 * inv, v1 * inv);
}

// ---------------- gate + interaction mixing + pooling (warp per graph)
__global__ void pool_kernel(const int* __restrict__ goff, const float* __restrict__ d_edge,
                            const float* __restrict__ w_d, const float* __restrict__ b_d,
                            const float* __restrict__ i_node, const float* __restrict__ W_i,
                            const float* __restrict__ h, float* __restrict__ pooled, int g_total) {
    int g = (blockIdx.x * blockDim.x + threadIdx.x) >> 5;
    int lane = threadIdx.x & 31;
    if (g >= g_total) return;
    float wd = w_d[0], bd = b_d[0];
    int beg = goff[g], end = goff[g + 1];
    float s00 = 0.f, s01 = 0.f, s10 = 0.f, s11 = 0.f, sg = 0.f;
    for (int nn = beg; nn < end; nn++) {
        float gate = 1.0f / (1.0f + __expf(-(d_edge[nn] * wd + bd)));
        float2 hp = *(const float2*)(h + (size_t)nn * H + 2 * lane);
        s00 += hp.x; s01 += hp.y;
        s10 += gate * hp.x; s11 += gate * hp.y;
        sg += gate;
    }
    float wi0 = W_i[2 * lane], wi1 = W_i[2 * lane + 1];
    float iv = i_node[g];
    float hi0 = iv * wi0 + s10;
    float hi1 = iv * wi1 + s11;
    *(float2*)(pooled + (size_t)g * H + 2 * lane) =
        make_float2(s00 + sg * hi0, s01 + sg * hi1);
}

// ---------------- MLP readout ----------------
__global__ void mlp_kernel(const float* __restrict__ pooled, const float* __restrict__ W_mlp,
                           const float* __restrict__ b_mlp, const float* __restrict__ W_out,
                           const float* __restrict__ b_out, float* __restrict__ out, int g_total) {
    __shared__ float sW[4096];
    __shared__ float sx[4][64];
    __shared__ float sb[64];
    __shared__ float sWo[64];
    __shared__ float red[8];
    int tid = threadIdx.x;
    int local = tid >> 6, j = tid & 63;
    if (tid < 64) sWo[tid] = W_out[tid];
    int ngroups = (g_total + 3) / 4;
    for (int grp = blockIdx.x; grp < ngroups; grp += gridDim.x) {
        int g = grp * 4 + local;
        __syncthreads();
        sx[local][j] = (g < g_total) ? pooled[(size_t)g * H + j] : 0.f;
        for (int i = 0; i < 3; i++) {
            __syncthreads();
            for (int t = tid; t < 4096; t += 256) sW[t] = W_mlp[i * 4096 + t];
            if (tid < 64) sb[tid] = b_mlp[i * 64 + tid];
            __syncthreads();
            float acc = sb[j];
            for (int k = 0; k < 64; k++) acc += sx[local][k] * sW[k * 64 + j];
            acc = fmaxf(acc, 0.f);
            __syncthreads();
            sx[local][j] = acc;
        }
        __syncthreads();
        float part = sx[local][j] * sWo[j];
        #pragma unroll
        for (int d = 16; d; d >>= 1) part += __shfl_xor_sync(0xffffffffu, part, d);
        if ((tid & 31) == 0) red[tid >> 5] = part;
        __syncthreads();
        if (j == 0 && g < g_total) out[g] = red[2 * local] + red[2 * local + 1] + b_out[0];
    }
}

// ---------------- launcher ----------------
extern "C" void kernel_launch(void* const* d_in, const int* in_sizes, int n_in,
                              void* d_out, int out_size) {
    const float* r_node  = (const float*)d_in[0];
    const float* i_node  = (const float*)d_in[1];
    const float* r_edge  = (const float*)d_in[2];
    const float* d_edge  = (const float*)d_in[3];
    const int*   r2r_src = (const int*)d_in[4];
    const int*   r2r_dst = (const int*)d_in[5];
    const int*   graph_id= (const int*)d_in[6];
    const float* W_r     = (const float*)d_in[7];
    const float* W_i     = (const float*)d_in[8];
    const float* W_e     = (const float*)d_in[9];
    const float* Wm      = (const float*)d_in[10];
    const float* a_s     = (const float*)d_in[11];
    const float* a_d     = (const float*)d_in[12];
    const float* a_e     = (const float*)d_in[13];
    const float* w_d     = (const float*)d_in[14];
    const float* b_d     = (const float*)d_in[15];
    const float* W_mlp   = (const float*)d_in[16];
    const float* b_mlp   = (const float*)d_in[17];
    const float* W_out   = (const float*)d_in[18];
    const float* b_out   = (const float*)d_in[19];
    float* out = (float*)d_out;

    const int nN = in_sizes[3];
    const int nE = in_sizes[4];
    const int nG = in_sizes[1];

    float *p_h, *p_agg, *p_hs, *p_hd, *p_ea, *p_w16, *p_pooled;
    __half2 *p_ecsr, *p_h16;
    int *p_deg, *p_off, *p_cur, *p_srcs, *p_perm, *p_gcnt, *p_goff, *p_bsums;
    cudaGetSymbolAddress((void**)&p_h, g_h);
    cudaGetSymbolAddress((void**)&p_h16, g_h16);
    cudaGetSymbolAddress((void**)&p_agg, g_agg);
    cudaGetSymbolAddress((void**)&p_hs, g_hs);
    cudaGetSymbolAddress((void**)&p_hd, g_hd);
    cudaGetSymbolAddress((void**)&p_ecsr, g_ecsr);
    cudaGetSymbolAddress((void**)&p_ea, g_ea);
    cudaGetSymbolAddress((void**)&p_w16, g_w16);
    cudaGetSymbolAddress((void**)&p_pooled, g_pooled);
    cudaGetSymbolAddress((void**)&p_deg, g_deg);
    cudaGetSymbolAddress((void**)&p_off, g_off);
    cudaGetSymbolAddress((void**)&p_cur, g_cur);
    cudaGetSymbolAddress((void**)&p_srcs, g_srcs);
    cudaGetSymbolAddress((void**)&p_perm, g_perm);
    cudaGetSymbolAddress((void**)&p_gcnt, g_gcnt);
    cudaGetSymbolAddress((void**)&p_goff, g_goff);
    cudaGetSymbolAddress((void**)&p_bsums, g_bsums);

    // --- node embedding FIRST (no CSR dependency) so ncu's capture window
    //     lands on a heavy kernel instead of hist_kernel ---
    matvec_kernel<<<592, 256>>>(r_node, W_r, nullptr, p_h, p_h16,
                                a_s, a_d, p_hs, p_hd, nN, 0);
    w16_kernel<<<1, 64>>>(W_e, a_e, p_w16);

    // --- CSR build ---
    zero_int<<<(nN + 255) / 256, 256>>>(p_deg, nN);
    zero_int<<<(nG + 255) / 256, 256>>>(p_gcnt, nG);
    hist_kernel<<<(nE + 255) / 256, 256>>>(r2r_dst, p_deg, nE);
    hist_kernel<<<(nN + 255) / 256, 256>>>(graph_id, p_gcnt, nN);

    int nbN = (nN + 1023) / 1024;
    scan_block<<<nbN, 1024>>>(p_deg, p_off, p_bsums, nN);
    scan_sums_serial<<<1, 32>>>(p_bsums, nbN);
    add_base<<<nbN, 1024>>>(p_off, p_bsums, nN);

    int nbG = (nG + 1023) / 1024;
    scan_block<<<nbG, 1024>>>(p_gcnt, p_goff, p_bsums, nG);
    scan_sums_serial<<<1, 32>>>(p_bsums, nbG);
    add_base<<<nbG, 1024>>>(p_goff, p_bsums, nG);

    copy_int<<<(nN + 255) / 256, 256>>>(p_cur, p_off, nN);
    scatter_kernel<<<(nE + 255) / 256, 256>>>(r2r_src, r2r_dst, p_cur, p_perm, p_srcs, nE);

    // --- edge embeddings + logit terms ---
    build_e_kernel<<<2048, 256>>>(r_edge, W_e, p_perm, p_w16, p_ecsr, p_ea, nE);

    // --- 4 attention conv layers ---
    int layer_blocks = (nN + 7) / 8;
    for (int l = 0; l < LYR; l++) {
        layer_kernel<<<layer_blocks, 256>>>(p_off, p_srcs, p_ea + (size_t)l * N_E,
                                            p_hs, p_hd, p_h16, p_ecsr, p_agg, nN);
        const float* as_next = (l < LYR - 1) ? (a_s + (l + 1) * H) : nullptr;
        const float* ad_next = (l < LYR - 1) ? (a_d + (l + 1) * H) : nullptr;
        matvec_kernel<<<592, 256>>>(p_agg, Wm + (size_t)l * H * H, p_h, p_h, p_h16,
                                    as_next, ad_next, p_hs, p_hd, nN, 1);
    }

    // --- gate / interaction mixing / pooling ---
    pool_kernel<<<(nG + 7) / 8, 256>>>(p_goff, d_edge, w_d, b_d, i_node, W_i,
                                       p_h, p_pooled, nG);

    // --- MLP readout ---
    mlp_kernel<<<64, 256>>>(p_pooled, W_mlp, b_mlp, W_out, b_out, out, nG);
}

// round 6
// speedup vs baseline: 1.2832x; 1.1026x over previous
#include <cuda_runtime.h>
#include <cuda_fp16.h>
#include <cstdint>

#define N_R   100000
#define N_E   1200000
#define G_N   4096
#define H     64
#define ED    16
#define LYR   4
#define CHUNK 128

// ---------------- scratch (device globals; allocation-free) ----------------
__device__ float   g_h[(size_t)N_R * H];
__device__ __half2 g_h16[(size_t)N_R * (H / 2)];
__device__ float   g_agg[(size_t)N_R * H];
__device__ float   g_hs[N_R];
__device__ float   g_hd[N_R];
__device__ __half2 g_ecsr[(size_t)N_E * (H / 2)];
__device__ float   g_ea[LYR * N_E];
__device__ int     g_deg[N_R];
__device__ int     g_off[N_R + 1];
__device__ int     g_cur[N_R];
__device__ int     g_srcs[N_E];
__device__ int     g_perm[N_E];
__device__ int     g_gcnt[G_N];
__device__ int     g_goff[G_N + 1];
__device__ float   g_w16[LYR * ED];
__device__ float   g_pooled[(size_t)G_N * H];
__device__ int     g_bsums[256];

__device__ __forceinline__ unsigned pack_half2(float a, float b) {
    __half2 h = __floats2half2_rn(a, b);
    return *reinterpret_cast<unsigned*>(&h);
}

// ---------------- small utility kernels ----------------
__global__ void zero_int(int* p, int n) {
    int i = blockIdx.x * blockDim.x + threadIdx.x;
    if (i < n) p[i] = 0;
}
__global__ void copy_int(int* dst, const int* src, int n) {
    int i = blockIdx.x * blockDim.x + threadIdx.x;
    if (i < n) dst[i] = src[i];
}
__global__ void hist_kernel(const int* __restrict__ idx, int* __restrict__ cnt, int n) {
    int i = blockIdx.x * blockDim.x + threadIdx.x;
    if (i < n) atomicAdd(&cnt[idx[i]], 1);
}

// ---- multi-block exclusive scan ----
__global__ void scan_block(const int* __restrict__ cnt, int* __restrict__ off,
                           int* __restrict__ sums, int n) {
    __shared__ int wsum[32];
    int tid = threadIdx.x;
    int i = blockIdx.x * 1024 + tid;
    int v = (i < n) ? cnt[i] : 0;
    int x = v;
    #pragma unroll
    for (int d = 1; d < 32; d <<= 1) {
        int y = __shfl_up_sync(0xffffffffu, x, d);
        if ((tid & 31) >= d) x += y;
    }
    if ((tid & 31) == 31) wsum[tid >> 5] = x;
    __syncthreads();
    if (tid < 32) {
        int w = wsum[tid];
        #pragma unroll
        for (int d = 1; d < 32; d <<= 1) {
            int y = __shfl_up_sync(0xffffffffu, w, d);
            if (tid >= d) w += y;
        }
        wsum[tid] = w;
    }
    __syncthreads();
    int incl = x + ((tid >= 32) ? wsum[(tid >> 5) - 1] : 0);
    if (i < n) off[i + 1] = incl;
    if (tid == 1023) sums[blockIdx.x] = incl;
}
// parallel exclusive scan of block sums (nb <= 128), single block of 128
__global__ void scan_sums_par(int* sums, int nb) {
    __shared__ int ws[4];
    int tid = threadIdx.x;
    int lane = tid & 31;
    int v = (tid < nb) ? sums[tid] : 0;
    int x = v;
    #pragma unroll
    for (int d = 1; d < 32; d <<= 1) {
        int y = __shfl_up_sync(0xffffffffu, x, d);
        if (lane >= d) x += y;
    }
    if (lane == 31) ws[tid >> 5] = x;
    __syncthreads();
    if (tid == 0) {
        int a = 0;
        #pragma unroll
        for (int j = 0; j < 4; j++) { int t = ws[j]; ws[j] = a; a += t; }
    }
    __syncthreads();
    x += ws[tid >> 5];
    if (tid < nb) sums[tid] = x - v;   // exclusive
}
__global__ void add_base(int* __restrict__ off, const int* __restrict__ sums, int n) {
    int i = blockIdx.x * 1024 + threadIdx.x;
    if (i == 0) off[0] = 0;
    if (i < n) off[i + 1] += sums[blockIdx.x];
}

__global__ void scatter_kernel(const int* __restrict__ src, const int* __restrict__ dst,
                               int* __restrict__ cur, int* __restrict__ perm,
                               int* __restrict__ srcs, int n) {
    int e = blockIdx.x * blockDim.x + threadIdx.x;
    if (e < n) {
        int d = dst[e];
        int p = atomicAdd(&cur[d], 1);
        perm[p] = e;
        srcs[p] = src[e];
    }
}

__global__ void w16_kernel(const float* __restrict__ W_e, const float* __restrict__ a_e,
                           float* __restrict__ w16) {
    int t = threadIdx.x;
    if (t < LYR * ED) {
        int l = t >> 4, k = t & 15;
        float s = 0.f;
        for (int j = 0; j < H; j++) s += W_e[k * H + j] * a_e[l * H + j];
        w16[t] = s;
    }
}

// ---------------- tensor-core node GEMM: out = maybe_lrelu(resid + in @ W) ----
// fp16 HMMA (m16n8k16), fp32 accumulate. W fragments live in registers for the
// whole kernel. hs/hd dots fused via smem reduction.
__global__ void __launch_bounds__(256)
gemm64_kernel(const float* __restrict__ in, const float* __restrict__ W,
              const float* __restrict__ resid, float* __restrict__ out,
              __half2* __restrict__ out16,
              const float* __restrict__ as_, const float* __restrict__ ad_,
              float* __restrict__ hs, float* __restrict__ hd,
              int n, int do_lrelu) {
    __shared__ float  sW[64 * 64];       // 16 KB staging for W
    __shared__ __half sA[64][72];        // 9.2 KB, pitch 72 halfs (conflict-free)
    __shared__ float  sRed[64][4];       // dot partials [row][cg*2 + {s,d}]
    int tid = threadIdx.x;
    int lane = tid & 31;
    int w = tid >> 5;
    int wr = (w & 3) * 16;               // row base within 64-node tile
    int cg = w >> 2;                     // column group: 0 -> cols 0..31, 1 -> 32..63

    // stage W, then build per-warp B fragments (held in registers throughout)
    for (int i = tid; i < 4096; i += 256) sW[i] = W[i];
    __syncthreads();
    unsigned bfr[4][4][2];               // [nfrag][kstep][2]
    {
        int col = cg * 32 + (lane >> 2); // + f*8
        int k0 = (lane & 3) * 2;
        #pragma unroll
        for (int f = 0; f < 4; f++) {
            int c = col + f * 8;
            #pragma unroll
            for (int s = 0; s < 4; s++) {
                int kk = s * 16 + k0;
                bfr[f][s][0] = pack_half2(sW[kk * 64 + c],       sW[(kk + 1) * 64 + c]);
                bfr[f][s][1] = pack_half2(sW[(kk + 8) * 64 + c], sW[(kk + 9) * 64 + c]);
            }
        }
    }

    float as0[8], ad0[8];                // per-col a_s/a_d for this lane's 8 cols
    if (as_) {
        #pragma unroll
        for (int f = 0; f < 4; f++) {
            int c = cg * 32 + f * 8 + 2 * (lane & 3);
            as0[2 * f]     = as_[c];     as0[2 * f + 1] = as_[c + 1];
            ad0[2 * f]     = ad_[c];     ad0[2 * f + 1] = ad_[c + 1];
        }
    }

    int ntiles = (n + 63) / 64;
    for (int t = blockIdx.x; t < ntiles; t += gridDim.x) {
        int base = t * 64;
        __syncthreads();
        // fill sA (fp32 -> fp16)
        for (int i = tid; i < 2048; i += 256) {
            int row = i >> 5;
            int k0 = (i & 31) * 2;
            int node = base + row;
            float2 v = (node < n) ? *(const float2*)(in + (size_t)node * H + k0)
                                  : make_float2(0.f, 0.f);
            *(__half2*)&sA[row][k0] = __floats2half2_rn(v.x, v.y);
        }
        __syncthreads();

        float c[4][4];
        #pragma unroll
        for (int f = 0; f < 4; f++)
            #pragma unroll
            for (int j = 0; j < 4; j++) c[f][j] = 0.f;

        int r = lane >> 2, k0 = (lane & 3) * 2;
        #pragma unroll
        for (int s = 0; s < 4; s++) {
            unsigned a0 = *(unsigned*)&sA[wr + r][s * 16 + k0];
            unsigned a1 = *(unsigned*)&sA[wr + r + 8][s * 16 + k0];
            unsigned a2 = *(unsigned*)&sA[wr + r][s * 16 + 8 + k0];
            unsigned a3 = *(unsigned*)&sA[wr + r + 8][s * 16 + 8 + k0];
            #pragma unroll
            for (int f = 0; f < 4; f++) {
                asm volatile(
                    "mma.sync.aligned.m16n8k16.row.col.f32.f16.f16.f32 "
                    "{%0,%1,%2,%3}, {%4,%5,%6,%7}, {%8,%9}, {%0,%1,%2,%3};"
                    : "+f"(c[f][0]), "+f"(c[f][1]), "+f"(c[f][2]), "+f"(c[f][3])
                    : "r"(a0), "r"(a1), "r"(a2), "r"(a3),
                      "r"(bfr[f][s][0]), "r"(bfr[f][s][1]));
            }
        }

        // epilogue
        int rowA = wr + (lane >> 2);         // tile-local rows
        int rowB = rowA + 8;
        int nodeA = base + rowA;
        int nodeB = base + rowB;
        float psA = 0.f, pdA = 0.f, psB = 0.f, pdB = 0.f;
        #pragma unroll
        for (int f = 0; f < 4; f++) {
            int col = cg * 32 + f * 8 + 2 * (lane & 3);
            float v0 = c[f][0], v1 = c[f][1];
            float u0 = c[f][2], u1 = c[f][3];
            if (resid) {
                if (nodeA < n) {
                    float2 rr = *(const float2*)(resid + (size_t)nodeA * H + col);
                    v0 += rr.x; v1 += rr.y;
                }
                if (nodeB < n) {
                    float2 rr = *(const float2*)(resid + (size_t)nodeB * H + col);
                    u0 += rr.x; u1 += rr.y;
                }
            }
            if (do_lrelu) {
                v0 = v0 > 0.f ? v0 : 0.1f * v0;  v1 = v1 > 0.f ? v1 : 0.1f * v1;
                u0 = u0 > 0.f ? u0 : 0.1f * u0;  u1 = u1 > 0.f ? u1 : 0.1f * u1;
            }
            if (nodeA < n) {
                *(float2*)(out + (size_t)nodeA * H + col) = make_float2(v0, v1);
                out16[(size_t)nodeA * 32 + (col >> 1)] = __floats2half2_rn(v0, v1);
            }
            if (nodeB < n) {
                *(float2*)(out + (size_t)nodeB * H + col) = make_float2(u0, u1);
                out16[(size_t)nodeB * 32 + (col >> 1)] = __floats2half2_rn(u0, u1);
            }
            if (as_) {
                psA += v0 * as0[2 * f] + v1 * as0[2 * f + 1];
                pdA += v0 * ad0[2 * f] + v1 * ad0[2 * f + 1];
                psB += u0 * as0[2 * f] + u1 * as0[2 * f + 1];
                pdB += u0 * ad0[2 * f] + u1 * ad0[2 * f + 1];
            }
        }
        if (as_) {
            // reduce across the 4 lanes sharing a row (lane%4 group)
            #pragma unroll
            for (int d = 1; d < 4; d <<= 1) {
                psA += __shfl_xor_sync(0xffffffffu, psA, d);
                pdA += __shfl_xor_sync(0xffffffffu, pdA, d);
                psB += __shfl_xor_sync(0xffffffffu, psB, d);
                pdB += __shfl_xor_sync(0xffffffffu, pdB, d);
            }
            if ((lane & 3) == 0) {
                sRed[rowA][cg * 2 + 0] = psA;  sRed[rowA][cg * 2 + 1] = pdA;
                sRed[rowB][cg * 2 + 0] = psB;  sRed[rowB][cg * 2 + 1] = pdB;
            }
            __syncthreads();
            if (tid < 64 && base + tid < n) {
                hs[base + tid] = sRed[tid][0] + sRed[tid][2];
                hd[base + tid] = sRed[tid][1] + sRed[tid][3];
            }
        }
    }
}

// ---------------- build edge embeddings (fp16, CSR order) + logit terms
__global__ void __launch_bounds__(256)
build_e_kernel(const float* __restrict__ r_edge,
               const float* __restrict__ W_e,
               const int* __restrict__ perm,
               const float* __restrict__ w16,
               __half2* __restrict__ ecsr, float* __restrict__ ea,
               int n_e) {
    __shared__ float sWe[ED * H];
    __shared__ float sw16[LYR * ED];
    for (int i = threadIdx.x; i < ED * H; i += 256) sWe[i] = W_e[i];
    if (threadIdx.x < LYR * ED) sw16[threadIdx.x] = w16[threadIdx.x];
    __syncthreads();
    int lane = threadIdx.x & 31;
    int warp = (blockIdx.x * blockDim.x + threadIdx.x) >> 5;
    int nwarps = (gridDim.x * blockDim.x) >> 5;
    const float2* sWe2 = (const float2*)sWe;
    for (int p = warp; p < n_e; p += nwarps) {
        int eid = __ldg(&perm[p]);
        const float4* rp = (const float4*)(r_edge + (size_t)eid * ED);
        float4 q0 = rp[0], q1 = rp[1], q2 = rp[2], q3 = rp[3];
        float r[16] = {q0.x, q0.y, q0.z, q0.w, q1.x, q1.y, q1.z, q1.w,
                       q2.x, q2.y, q2.z, q2.w, q3.x, q3.y, q3.z, q3.w};
        float e0 = 0.f, e1 = 0.f;
        #pragma unroll
        for (int k = 0; k < 16; k++) {
            float2 wp = sWe2[k * 32 + lane];
            e0 += r[k] * wp.x;
            e1 += r[k] * wp.y;
        }
        ecsr[(size_t)p * 32 + lane] = __floats2half2_rn(e0, e1);
        if (lane < LYR) {
            float s = 0.f;
            #pragma unroll
            for (int k = 0; k < 16; k++) s += r[k] * sw16[lane * ED + k];
            ea[(size_t)lane * N_E + p] = s;
        }
    }
}

// ---------------- fused attention layer (R2 structure, fp16 operands) --------
__global__ void __launch_bounds__(256)
layer_kernel(const int* __restrict__ off, const int* __restrict__ srcs,
             const float* __restrict__ ea, const float* __restrict__ hs,
             const float* __restrict__ hd, const __half2* __restrict__ h16,
             const __half2* __restrict__ ecsr, float* __restrict__ agg, int n) {
    __shared__ float s_w[8][CHUNK];
    __shared__ int   s_src[8][CHUNK];
    int wl = threadIdx.x >> 5;
    int lane = threadIdx.x & 31;
    int node = (blockIdx.x * blockDim.x + threadIdx.x) >> 5;
    if (node >= n) return;
    int beg = off[node], end = off[node + 1];
    float hdn = hd[node];
    float m_run = -1e30f, s_run = 0.f, v0 = 0.f, v1 = 0.f;
    for (int cs = beg; cs < end; cs += CHUNK) {
        int cnt = min(CHUNK, end - cs);
        float mloc = -1e30f;
        for (int i = lane; i < cnt; i += 32) {
            int p = cs + i;
            int sv = __ldg(&srcs[p]);
            float lg = __ldg(&hs[sv]) + hdn + __ldg(&ea[p]);
            lg = lg > 0.f ? lg : 0.1f * lg;
            s_w[wl][i] = lg;
            s_src[wl][i] = sv;
            mloc = fmaxf(mloc, lg);
        }
        #pragma unroll
        for (int d = 16; d; d >>= 1) mloc = fmaxf(mloc, __shfl_xor_sync(0xffffffffu, mloc, d));
        float mn = fmaxf(m_run, mloc);
        __syncwarp();
        float sloc = 0.f;
        for (int i = lane; i < cnt; i += 32) {
            float wv = __expf(s_w[wl][i] - mn);
            s_w[wl][i] = wv;
            sloc += wv;
        }
        #pragma unroll
        for (int d = 16; d; d >>= 1) sloc += __shfl_xor_sync(0xffffffffu, sloc, d);
        float c = __expf(m_run - mn);
        s_run = s_run * c + sloc;
        v0 *= c; v1 *= c;
        __syncwarp();
        #pragma unroll 4
        for (int i = 0; i < cnt; i++) {
            float wv = s_w[wl][i];
            int sv = s_src[wl][i];
            float2 hp = __half22float2(h16[(size_t)sv * 32 + lane]);
            float2 ep = __half22float2(ecsr[(size_t)(cs + i) * 32 + lane]);
            v0 += wv * (hp.x + ep.x);
            v1 += wv * (hp.y + ep.y);
        }
        m_run = mn;
    }
    float inv = (end > beg) ? (1.0f / s_run) : 0.f;
    *(float2*)(agg + (size_t)node * H + 2 * lane) = make_float2(v0 * inv, v1 * inv);
}

// ---------------- gate + interaction mixing + pooling (warp per graph)
__global__ void pool_kernel(const int* __restrict__ goff, const float* __restrict__ d_edge,
                            const float* __restrict__ w_d, const float* __restrict__ b_d,
                            const float* __restrict__ i_node, const float* __restrict__ W_i,
                            const float* __restrict__ h, float* __restrict__ pooled, int g_total) {
    int g = (blockIdx.x * blockDim.x + threadIdx.x) >> 5;
    int lane = threadIdx.x & 31;
    if (g >= g_total) return;
    float wd = w_d[0], bd = b_d[0];
    int beg = goff[g], end = goff[g + 1];
    float s00 = 0.f, s01 = 0.f, s10 = 0.f, s11 = 0.f, sg = 0.f;
    #pragma unroll 4
    for (int nn = beg; nn < end; nn++) {
        float gate = 1.0f / (1.0f + __expf(-(d_edge[nn] * wd + bd)));
        float2 hp = *(const float2*)(h + (size_t)nn * H + 2 * lane);
        s00 += hp.x; s01 += hp.y;
        s10 += gate * hp.x; s11 += gate * hp.y;
        sg += gate;
    }
    float wi0 = W_i[2 * lane], wi1 = W_i[2 * lane + 1];
    float iv = i_node[g];
    float hi0 = iv * wi0 + s10;
    float hi1 = iv * wi1 + s11;
    *(float2*)(pooled + (size_t)g * H + 2 * lane) =
        make_float2(s00 + sg * hi0, s01 + sg * hi1);
}

// ---------------- MLP readout ----------------
__global__ void mlp_kernel(const float* __restrict__ pooled, const float* __restrict__ W_mlp,
                           const float* __restrict__ b_mlp, const float* __restrict__ W_out,
                           const float* __restrict__ b_out, float* __restrict__ out, int g_total) {
    __shared__ float sW[4096];
    __shared__ float sx[4][64];
    __shared__ float sb[64];
    __shared__ float sWo[64];
    __shared__ float red[8];
    int tid = threadIdx.x;
    int local = tid >> 6, j = tid & 63;
    if (tid < 64) sWo[tid] = W_out[tid];
    int ngroups = (g_total + 3) / 4;
    for (int grp = blockIdx.x; grp < ngroups; grp += gridDim.x) {
        int g = grp * 4 + local;
        __syncthreads();
        sx[local][j] = (g < g_total) ? pooled[(size_t)g * H + j] : 0.f;
        for (int i = 0; i < 3; i++) {
            __syncthreads();
            for (int t = tid; t < 4096; t += 256) sW[t] = W_mlp[i * 4096 + t];
            if (tid < 64) sb[tid] = b_mlp[i * 64 + tid];
            __syncthreads();
            float acc = sb[j];
            for (int k = 0; k < 64; k++) acc += sx[local][k] * sW[k * 64 + j];
            acc = fmaxf(acc, 0.f);
            __syncthreads();
            sx[local][j] = acc;
        }
        __syncthreads();
        float part = sx[local][j] * sWo[j];
        #pragma unroll
        for (int d = 16; d; d >>= 1) part += __shfl_xor_sync(0xffffffffu, part, d);
        if ((tid & 31) == 0) red[tid >> 5] = part;
        __syncthreads();
        if (j == 0 && g < g_total) out[g] = red[2 * local] + red[2 * local + 1] + b_out[0];
    }
}

// ---------------- launcher ----------------
extern "C" void kernel_launch(void* const* d_in, const int* in_sizes, int n_in,
                              void* d_out, int out_size) {
    const float* r_node  = (const float*)d_in[0];
    const float* i_node  = (const float*)d_in[1];
    const float* r_edge  = (const float*)d_in[2];
    const float* d_edge  = (const float*)d_in[3];
    const int*   r2r_src = (const int*)d_in[4];
    const int*   r2r_dst = (const int*)d_in[5];
    const int*   graph_id= (const int*)d_in[6];
    const float* W_r     = (const float*)d_in[7];
    const float* W_i     = (const float*)d_in[8];
    const float* W_e     = (const float*)d_in[9];
    const float* Wm      = (const float*)d_in[10];
    const float* a_s     = (const float*)d_in[11];
    const float* a_d     = (const float*)d_in[12];
    const float* a_e     = (const float*)d_in[13];
    const float* w_d     = (const float*)d_in[14];
    const float* b_d     = (const float*)d_in[15];
    const float* W_mlp   = (const float*)d_in[16];
    const float* b_mlp   = (const float*)d_in[17];
    const float* W_out   = (const float*)d_in[18];
    const float* b_out   = (const float*)d_in[19];
    float* out = (float*)d_out;

    const int nN = in_sizes[3];
    const int nE = in_sizes[4];
    const int nG = in_sizes[1];

    float *p_h, *p_agg, *p_hs, *p_hd, *p_ea, *p_w16, *p_pooled;
    __half2 *p_ecsr, *p_h16;
    int *p_deg, *p_off, *p_cur, *p_srcs, *p_perm, *p_gcnt, *p_goff, *p_bsums;
    cudaGetSymbolAddress((void**)&p_h, g_h);
    cudaGetSymbolAddress((void**)&p_h16, g_h16);
    cudaGetSymbolAddress((void**)&p_agg, g_agg);
    cudaGetSymbolAddress((void**)&p_hs, g_hs);
    cudaGetSymbolAddress((void**)&p_hd, g_hd);
    cudaGetSymbolAddress((void**)&p_ecsr, g_ecsr);
    cudaGetSymbolAddress((void**)&p_ea, g_ea);
    cudaGetSymbolAddress((void**)&p_w16, g_w16);
    cudaGetSymbolAddress((void**)&p_pooled, g_pooled);
    cudaGetSymbolAddress((void**)&p_deg, g_deg);
    cudaGetSymbolAddress((void**)&p_off, g_off);
    cudaGetSymbolAddress((void**)&p_cur, g_cur);
    cudaGetSymbolAddress((void**)&p_srcs, g_srcs);
    cudaGetSymbolAddress((void**)&p_perm, g_perm);
    cudaGetSymbolAddress((void**)&p_gcnt, g_gcnt);
    cudaGetSymbolAddress((void**)&p_goff, g_goff);
    cudaGetSymbolAddress((void**)&p_bsums, g_bsums);

    // launches 0-2: setup; launch 3 = gemm64 (ncu capture window = index 3)
    zero_int<<<(nN + 255) / 256, 256>>>(p_deg, nN);
    zero_int<<<(nG + 255) / 256, 256>>>(p_gcnt, nG);
    hist_kernel<<<(nE + 255) / 256, 256>>>(r2r_dst, p_deg, nE);
    gemm64_kernel<<<592, 256>>>(r_node, W_r, nullptr, p_h, p_h16,
                                a_s, a_d, p_hs, p_hd, nN, 0);
    hist_kernel<<<(nN + 255) / 256, 256>>>(graph_id, p_gcnt, nN);

    int nbN = (nN + 1023) / 1024;
    scan_block<<<nbN, 1024>>>(p_deg, p_off, p_bsums, nN);
    scan_sums_par<<<1, 128>>>(p_bsums, nbN);
    add_base<<<nbN, 1024>>>(p_off, p_bsums, nN);

    int nbG = (nG + 1023) / 1024;
    scan_block<<<nbG, 1024>>>(p_gcnt, p_goff, p_bsums, nG);
    scan_sums_par<<<1, 128>>>(p_bsums, nbG);
    add_base<<<nbG, 1024>>>(p_goff, p_bsums, nG);

    copy_int<<<(nN + 255) / 256, 256>>>(p_cur, p_off, nN);
    scatter_kernel<<<(nE + 255) / 256, 256>>>(r2r_src, r2r_dst, p_cur, p_perm, p_srcs, nE);

    w16_kernel<<<1, 64>>>(W_e, a_e, p_w16);
    build_e_kernel<<<2048, 256>>>(r_edge, W_e, p_perm, p_w16, p_ecsr, p_ea, nE);

    // --- 4 attention conv layers ---
    int layer_blocks = (nN + 7) / 8;
    for (int l = 0; l < LYR; l++) {
        layer_kernel<<<layer_blocks, 256>>>(p_off, p_srcs, p_ea + (size_t)l * N_E,
                                            p_hs, p_hd, p_h16, p_ecsr, p_agg, nN);
        const float* as_next = (l < LYR - 1) ? (a_s + (l + 1) * H) : nullptr;
        const float* ad_next = (l < LYR - 1) ? (a_d + (l + 1) * H) : nullptr;
        gemm64_kernel<<<592, 256>>>(p_agg, Wm + (size_t)l * H * H, p_h, p_h, p_h16,
                                    as_next, ad_next, p_hs, p_hd, nN, 1);
    }

    // --- gate / interaction mixing / pooling ---
    pool_kernel<<<(nG + 7) / 8, 256>>>(p_goff, d_edge, w_d, b_d, i_node, W_i,
                                       p_h, p_pooled, nG);

    // --- MLP readout ---
    mlp_kernel<<<256, 256>>>(p_pooled, W_mlp, b_mlp, W_out, b_out, out, nG);
}